// round 1
// baseline (speedup 1.0000x reference)
#include <cuda_runtime.h>

#define D_IN     256
#define A_ATT    128
#define W_WIN    64
#define T_LEN    4096
#define B_BATCH  32
#define ROWS_BLK 64
#define WP_STRIDE 260   // 256 + 4 pad -> conflict-free LDS.128 across lanes
#define TT       256    // t-tile for window kernel

// gate scratch: B*T floats = 512 KB (device global, allocation-free)
__device__ float g_gate[B_BATCH * T_LEN];

__device__ __forceinline__ float tanh_fast(float v) {
    float y;
    asm("tanh.approx.f32 %0, %1;" : "=f"(y) : "f"(v));
    return y;
}

// ---------------------------------------------------------------------------
// Stage A: g[b,t] = sigmoid( Wg . tanh(Wp x + bp) )
// One block = 64 rows of (b,t). Wp and x tile staged in shared memory.
// Warp w owns rows [w*8, w*8+8); lane l owns A-columns {l, l+32, l+64, l+96}.
// ---------------------------------------------------------------------------
__global__ void __launch_bounds__(256, 1) gate_kernel(
    const float* __restrict__ x, const float* __restrict__ Wp,
    const float* __restrict__ bp, const float* __restrict__ Wg)
{
    extern __shared__ float sm[];
    float* Wps = sm;                       // [128][260]
    float* xs  = sm + A_ATT * WP_STRIDE;   // [64][256]
    const int tid = threadIdx.x;

    // stage Wp (padded rows, float4)
    for (int i = tid; i < A_ATT * (D_IN / 4); i += 256) {
        const int row = i >> 6, c4 = i & 63;
        float4 v = *(const float4*)(Wp + row * D_IN + c4 * 4);
        *(float4*)(Wps + row * WP_STRIDE + c4 * 4) = v;
    }
    // stage x tile
    const int row0 = blockIdx.x * ROWS_BLK;
    const float* xblk = x + (size_t)row0 * D_IN;
    for (int i = tid; i < ROWS_BLK * (D_IN / 4); i += 256) {
        const int r = i >> 6, c4 = i & 63;
        float4 v = *(const float4*)(xblk + r * D_IN + c4 * 4);
        *(float4*)(xs + r * D_IN + c4 * 4) = v;
    }
    __syncthreads();

    const int warp = tid >> 5, lane = tid & 31;
    const int r0 = warp * 8;

    float acc[8][4];
    #pragma unroll
    for (int i = 0; i < 4; i++) {
        const float b = __ldg(bp + lane + 32 * i);
        #pragma unroll
        for (int j = 0; j < 8; j++) acc[j][i] = b;
    }

    for (int d4 = 0; d4 < D_IN / 4; d4++) {
        float4 wv[4];
        #pragma unroll
        for (int i = 0; i < 4; i++)
            wv[i] = *(const float4*)(Wps + (lane + 32 * i) * WP_STRIDE + d4 * 4);
        #pragma unroll
        for (int j = 0; j < 8; j++) {
            const float4 xv = *(const float4*)(xs + (r0 + j) * D_IN + d4 * 4);
            #pragma unroll
            for (int i = 0; i < 4; i++) {
                acc[j][i] = fmaf(xv.x, wv[i].x, acc[j][i]);
                acc[j][i] = fmaf(xv.y, wv[i].y, acc[j][i]);
                acc[j][i] = fmaf(xv.z, wv[i].z, acc[j][i]);
                acc[j][i] = fmaf(xv.w, wv[i].w, acc[j][i]);
            }
        }
    }

    float wg[4];
    #pragma unroll
    for (int i = 0; i < 4; i++) wg[i] = __ldg(Wg + lane + 32 * i);

    float part[8];
    #pragma unroll
    for (int j = 0; j < 8; j++) {
        float s = 0.f;
        #pragma unroll
        for (int i = 0; i < 4; i++) s = fmaf(wg[i], tanh_fast(acc[j][i]), s);
        part[j] = s;
    }
    #pragma unroll
    for (int off = 16; off > 0; off >>= 1) {
        #pragma unroll
        for (int j = 0; j < 8; j++)
            part[j] += __shfl_xor_sync(0xffffffffu, part[j], off);
    }
    if (lane == 0) {
        #pragma unroll
        for (int j = 0; j < 8; j++)
            g_gate[row0 + r0 + j] = 1.f / (1.f + __expf(-part[j]));
    }
}

// ---------------------------------------------------------------------------
// Stage B: sliding causal window sum, window = 64 (inclusive of t).
// Block = (t-tile of 256, batch b). Thread = channel d. Running add/subtract.
// ---------------------------------------------------------------------------
__global__ void __launch_bounds__(256, 1) window_kernel(
    const float* __restrict__ x, float* __restrict__ out)
{
    const int b  = blockIdx.y;
    const int t0 = blockIdx.x * TT;
    const int d  = threadIdx.x;

    __shared__ float gs[TT + W_WIN - 1];   // g[t0-63 .. t0+255]
    for (int i = threadIdx.x; i < TT + W_WIN - 1; i += 256) {
        const int t = t0 - (W_WIN - 1) + i;
        gs[i] = (t >= 0) ? g_gate[b * T_LEN + t] : 0.f;
    }
    __syncthreads();

    const float* xb = x   + ((size_t)b * T_LEN) * D_IN + d;
    float*       ob = out + ((size_t)b * T_LEN) * D_IN + d;

    float num = 0.f, den = 0.f;

    // prefill window tail [t0-63, t0-1]
    #pragma unroll 1
    for (int i = 0; i < W_WIN - 1; i++) {
        const int t = t0 - (W_WIN - 1) + i;
        if (t >= 0) {
            const float gv = gs[i];
            num = fmaf(gv, xb[(size_t)t * D_IN], num);
            den += gv;
        }
    }
    // slide over the tile
    #pragma unroll 1
    for (int i = 0; i < TT; i++) {
        const int t = t0 + i;
        const float gv = gs[(W_WIN - 1) + i];
        num = fmaf(gv, xb[(size_t)t * D_IN], num);
        den += gv;
        ob[(size_t)t * D_IN] = num / den;
        const int tr = t - (W_WIN - 1);
        if (tr >= 0) {
            const float gr = gs[i];
            num = fmaf(-gr, xb[(size_t)tr * D_IN], num);
            den -= gr;
        }
    }
}

// ---------------------------------------------------------------------------
extern "C" void kernel_launch(void* const* d_in, const int* in_sizes, int n_in,
                              void* d_out, int out_size)
{
    const float* x  = (const float*)d_in[0];
    const float* Wp = (const float*)d_in[1];
    const float* bp = (const float*)d_in[2];
    const float* Wg = (const float*)d_in[3];
    float* out = (float*)d_out;

    const int rows_total = in_sizes[0] / D_IN;          // B*T
    const int gate_blocks = rows_total / ROWS_BLK;       // 2048
    const int batches = rows_total / T_LEN;              // 32

    const int smem = (A_ATT * WP_STRIDE + ROWS_BLK * D_IN) * (int)sizeof(float); // 198656
    cudaFuncSetAttribute(gate_kernel,
                         cudaFuncAttributeMaxDynamicSharedMemorySize, smem);

    gate_kernel<<<gate_blocks, 256, smem>>>(x, Wp, bp, Wg);

    dim3 wgrid(T_LEN / TT, batches);
    window_kernel<<<wgrid, 256>>>(x, out);
}

// round 3
// speedup vs baseline: 4.5323x; 4.5323x over previous
#include <cuda_runtime.h>
#include <cstdint>

#define D_IN     256
#define A_ATT    128
#define W_WIN    64
#define T_LEN    4096
#define B_BATCH  32
#define TT       256     // t-tile for window kernel
#define M_TILE   64      // rows per gate tile

// gate scratch: B*T floats = 512 KB (device global, allocation-free)
__device__ float g_gate[B_BATCH * T_LEN];

// ---------------------------------------------------------------------------
// helpers
// ---------------------------------------------------------------------------
__device__ __forceinline__ uint32_t smem_u32(const void* p) {
    uint32_t a;
    asm("{ .reg .u64 t; cvta.to.shared.u64 t, %1; cvt.u32.u64 %0, t; }" : "=r"(a) : "l"(p));
    return a;
}
__device__ __forceinline__ float tanh_fast(float v) {
    float y; asm("tanh.approx.f32 %0, %1;" : "=f"(y) : "f"(v)); return y;
}
__device__ __forceinline__ uint32_t f2tf32(float v) {
    uint32_t u; asm("cvt.rna.tf32.f32 %0, %1;" : "=r"(u) : "f"(v)); return u;
}
__device__ __forceinline__ void mma_tf32(float* c, const uint32_t* a, const uint32_t* b) {
    asm volatile("mma.sync.aligned.m16n8k8.row.col.f32.tf32.tf32.f32 "
                 "{%0,%1,%2,%3}, {%4,%5,%6,%7}, {%8,%9}, {%0,%1,%2,%3};"
                 : "+f"(c[0]), "+f"(c[1]), "+f"(c[2]), "+f"(c[3])
                 : "r"(a[0]), "r"(a[1]), "r"(a[2]), "r"(a[3]), "r"(b[0]), "r"(b[1]));
}
#define CP_COMMIT() asm volatile("cp.async.commit_group;" ::: "memory")
#define CP_WAIT1()  asm volatile("cp.async.wait_group 1;" ::: "memory")

// ---------------------------------------------------------------------------
// SMEM layout (dynamic, bytes):
//  Wps  [0, 131072)        : Wp as tf32 bits, 128 n-rows x 256 k (swizzled)
//  xs0  [131072, 163840)   : x half-K buffer 0: 64 rows x 128 k (swizzled)
//  xs1  [163840, 196608)   : x half-K buffer 1
//  bwv  [196608, 197632)   : 128 x float2 {bp, Wg}
//  red  [197632, 198656)   : 4 x 64 cross-warp partials
// ---------------------------------------------------------------------------
#define SM_WP   0
#define SM_X0   131072
#define SM_X1   163840
#define SM_BW   196608
#define SM_RED  197632
#define SM_TOT  198656

__global__ void __launch_bounds__(256, 1) gate_kernel(
    const float* __restrict__ x, const float* __restrict__ Wp,
    const float* __restrict__ bp, const float* __restrict__ Wg, int ntiles)
{
    extern __shared__ char smem[];
    uint32_t*     Wps = (uint32_t*)(smem + SM_WP);
    const float*  xsf[2] = { (const float*)(smem + SM_X0), (const float*)(smem + SM_X1) };
    float2*       bwv = (float2*)(smem + SM_BW);
    float*        red = (float*)(smem + SM_RED);

    const int tid = threadIdx.x, wid = tid >> 5, lane = tid & 31;
    const int lane4 = lane >> 2, lanek = lane & 3;
    const int wm = wid & 1, wn = wid >> 1;
    const uint32_t m = (uint32_t)(lane4 << 2);     // swizzle mask (row&7)<<2 == lane4<<2

    // stage Wp with rna tf32 rounding, swizzled (float off = f ^ ((n&7)<<2))
    for (int i = tid; i < 128 * 64; i += 256) {
        const int n = i >> 6, c4 = i & 63;
        const float4 v = *(const float4*)(Wp + n * D_IN + c4 * 4);
        uint4 u;
        u.x = f2tf32(v.x); u.y = f2tf32(v.y); u.z = f2tf32(v.z); u.w = f2tf32(v.w);
        *(uint4*)((char*)Wps + n * 1024 + ((c4 ^ (n & 7)) << 4)) = u;
    }
    if (tid < 128) { float2 bw; bw.x = bp[tid]; bw.y = Wg[tid]; bwv[tid] = bw; }

    const uint32_t xs_u[2] = { smem_u32(xsf[0]), smem_u32(xsf[1]) };

    auto issue_half = [&](int tile, int h) {
        const float* xg = x + (size_t)tile * M_TILE * D_IN + h * 128;
        #pragma unroll
        for (int j = 0; j < 8; j++) {
            const int idx = tid + j * 256;            // 0..2047 float4s
            const int row = idx >> 5, c4 = idx & 31;
            const uint32_t dst = xs_u[h] + row * 512 + ((c4 ^ (row & 7)) << 4);
            asm volatile("cp.async.cg.shared.global [%0], [%1], 16;"
                         :: "r"(dst), "l"(xg + row * 256 + c4 * 4));
        }
        CP_COMMIT();
    };

    // per-thread fragment bases
    int xrow[2][2];
    #pragma unroll
    for (int mt = 0; mt < 2; mt++)
        #pragma unroll
        for (int rh = 0; rh < 2; rh++)
            xrow[mt][rh] = (wm * 32 + mt * 16 + rh * 8 + lane4) * 128;
    int bn[4];
    #pragma unroll
    for (int nt = 0; nt < 4; nt++) bn[nt] = (wn * 32 + nt * 8 + lane4) * 256;

    auto compute_half = [&](int h, float (&acc)[2][4][4]) {
        const float* xb = xsf[h];
        const int kb = h * 128;
        #pragma unroll
        for (int k0 = 0; k0 < 128; k0 += 8) {
            uint32_t a[2][4];
            #pragma unroll
            for (int mt = 0; mt < 2; mt++) {
                a[mt][0] = f2tf32(xb[xrow[mt][0] + (((k0     + lanek)) ^ m)]);
                a[mt][1] = f2tf32(xb[xrow[mt][1] + (((k0     + lanek)) ^ m)]);
                a[mt][2] = f2tf32(xb[xrow[mt][0] + (((k0 + 4 + lanek)) ^ m)]);
                a[mt][3] = f2tf32(xb[xrow[mt][1] + (((k0 + 4 + lanek)) ^ m)]);
            }
            uint32_t b[4][2];
            #pragma unroll
            for (int nt = 0; nt < 4; nt++) {
                b[nt][0] = Wps[bn[nt] + (((kb + k0     + lanek)) ^ m)];
                b[nt][1] = Wps[bn[nt] + (((kb + k0 + 4 + lanek)) ^ m)];
            }
            #pragma unroll
            for (int mt = 0; mt < 2; mt++)
                #pragma unroll
                for (int nt = 0; nt < 4; nt++)
                    mma_tf32(acc[mt][nt], a[mt], b[nt]);
        }
    };

    const int iters = (ntiles - blockIdx.x + gridDim.x - 1) / gridDim.x;
    if (iters > 0) { issue_half(blockIdx.x, 0); issue_half(blockIdx.x, 1); }

    for (int i = 0; i < iters; i++) {
        const int tile  = blockIdx.x + i * gridDim.x;
        const int ntile = tile + gridDim.x;
        float acc[2][4][4];
        #pragma unroll
        for (int mt = 0; mt < 2; mt++)
            #pragma unroll
            for (int nt = 0; nt < 4; nt++)
                #pragma unroll
                for (int c = 0; c < 4; c++) acc[mt][nt][c] = 0.f;

        // half 0
        CP_WAIT1(); __syncthreads();
        compute_half(0, acc);
        __syncthreads();
        if (i + 1 < iters) issue_half(ntile, 0); else CP_COMMIT();

        // half 1
        CP_WAIT1(); __syncthreads();
        compute_half(1, acc);

        // epilogue: s[row] = sum_col Wg[col]*tanh(P+bp[col])
        float s[2][2] = {{0.f, 0.f}, {0.f, 0.f}};
        #pragma unroll
        for (int mt = 0; mt < 2; mt++)
            #pragma unroll
            for (int nt = 0; nt < 4; nt++) {
                const int colb = wn * 32 + nt * 8 + 2 * lanek;
                const float2 bw0 = bwv[colb], bw1 = bwv[colb + 1];
                s[mt][0] = fmaf(bw0.y, tanh_fast(acc[mt][nt][0] + bw0.x),
                           fmaf(bw1.y, tanh_fast(acc[mt][nt][1] + bw1.x), s[mt][0]));
                s[mt][1] = fmaf(bw0.y, tanh_fast(acc[mt][nt][2] + bw0.x),
                           fmaf(bw1.y, tanh_fast(acc[mt][nt][3] + bw1.x), s[mt][1]));
            }
        #pragma unroll
        for (int off = 1; off <= 2; off <<= 1) {
            #pragma unroll
            for (int mt = 0; mt < 2; mt++) {
                s[mt][0] += __shfl_xor_sync(0xffffffffu, s[mt][0], off);
                s[mt][1] += __shfl_xor_sync(0xffffffffu, s[mt][1], off);
            }
        }
        if (lanek == 0) {
            #pragma unroll
            for (int mt = 0; mt < 2; mt++)
                #pragma unroll
                for (int rh = 0; rh < 2; rh++)
                    red[wn * 64 + wm * 32 + mt * 16 + rh * 8 + lane4] = s[mt][rh];
        }
        __syncthreads();
        if (tid < 64) {
            const float t = red[tid] + red[64 + tid] + red[128 + tid] + red[192 + tid];
            g_gate[tile * M_TILE + tid] = 1.f / (1.f + __expf(-t));
        }
        __syncthreads();
        if (i + 1 < iters) issue_half(ntile, 1); else CP_COMMIT();
    }
}

// ---------------------------------------------------------------------------
// Stage B: sliding causal window, window=64. Block = (t-tile 256, batch b),
// thread = channel d. inv_den precomputed (d-independent); loads batched x8.
// ---------------------------------------------------------------------------
__global__ void __launch_bounds__(256, 1) window_kernel(
    const float* __restrict__ x, float* __restrict__ out)
{
    const int b  = blockIdx.y;
    const int t0 = blockIdx.x * TT;
    const int d  = threadIdx.x;

    __shared__ float gs[TT + W_WIN - 1];   // g[t0-63 .. t0+255]; 0 for t<0
    __shared__ float rinv[TT];
    for (int i = threadIdx.x; i < TT + W_WIN - 1; i += 256) {
        const int t = t0 - (W_WIN - 1) + i;
        gs[i] = (t >= 0) ? g_gate[b * T_LEN + t] : 0.f;
    }
    __syncthreads();
    {   // den for output index i = sum gs[i .. i+63]
        float den = 0.f;
        #pragma unroll 8
        for (int j = 0; j < W_WIN; j++) den += gs[d + j];
        rinv[d] = __frcp_rn(den);
    }
    __syncthreads();

    const float* xb = x   + ((size_t)b * T_LEN) * D_IN + d;
    float*       ob = out + ((size_t)b * T_LEN) * D_IN + d;

    float num = 0.f;
    // prefill window tail [t0-63, t0-1]; gs already 0 for t<0, clamp address only
    #pragma unroll
    for (int j = 0; j < W_WIN - 1; j++) {
        const int t = t0 - (W_WIN - 1) + j;
        const int tc = t < 0 ? 0 : t;
        num = fmaf(gs[j], xb[(size_t)tc * D_IN], num);
    }

    // main loop: batches of 8 with independent loads (MLP=8)
    #pragma unroll 1
    for (int i0 = 0; i0 < TT; i0 += 8) {
        float xa[8], xsub[8];
        #pragma unroll
        for (int u = 0; u < 8; u++)
            xa[u] = xb[(size_t)(t0 + i0 + u) * D_IN];
        #pragma unroll
        for (int u = 0; u < 8; u++) {
            const int tr = t0 + i0 + u - (W_WIN - 1);
            const int trc = tr < 0 ? 0 : tr;
            xsub[u] = xb[(size_t)trc * D_IN];
        }
        #pragma unroll
        for (int u = 0; u < 8; u++) {
            const int i = i0 + u;
            num = fmaf(gs[(W_WIN - 1) + i], xa[u], num);
            ob[(size_t)(t0 + i) * D_IN] = num * rinv[i];
            num = fmaf(-gs[i], xsub[u], num);   // gs[i]=0 when t-63<0
        }
    }
}

// ---------------------------------------------------------------------------
extern "C" void kernel_launch(void* const* d_in, const int* in_sizes, int n_in,
                              void* d_out, int out_size)
{
    const float* x  = (const float*)d_in[0];
    const float* Wp = (const float*)d_in[1];
    const float* bp = (const float*)d_in[2];
    const float* Wg = (const float*)d_in[3];
    float* out = (float*)d_out;

    const int rows_total = in_sizes[0] / D_IN;   // B*T
    const int ntiles = rows_total / M_TILE;      // 2048
    const int batches = rows_total / T_LEN;      // 32

    int nsm = 148;
    cudaDeviceGetAttribute(&nsm, cudaDevAttrMultiProcessorCount, 0);
    const int grid = nsm < ntiles ? nsm : ntiles;

    cudaFuncSetAttribute(gate_kernel,
                         cudaFuncAttributeMaxDynamicSharedMemorySize, SM_TOT);
    gate_kernel<<<grid, 256, SM_TOT>>>(x, Wp, bp, Wg, ntiles);

    dim3 wgrid(T_LEN / TT, batches);
    window_kernel<<<wgrid, 256>>>(x, out);
}

// round 4
// speedup vs baseline: 4.7694x; 1.0523x over previous
#include <cuda_runtime.h>
#include <cstdint>

#define D_IN     256
#define A_ATT    128
#define W_WIN    64
#define T_LEN    4096
#define B_BATCH  32
#define TT       256     // t-tile for window kernel
#define M_TILE   64      // rows per gate tile

// gate scratch: B*T floats = 512 KB (device global, allocation-free)
__device__ float g_gate[B_BATCH * T_LEN];

// ---------------------------------------------------------------------------
// helpers
// ---------------------------------------------------------------------------
__device__ __forceinline__ uint32_t smem_u32(const void* p) {
    uint32_t a;
    asm("{ .reg .u64 t; cvta.to.shared.u64 t, %1; cvt.u32.u64 %0, t; }" : "=r"(a) : "l"(p));
    return a;
}
__device__ __forceinline__ float tanh_fast(float v) {
    float y; asm("tanh.approx.f32 %0, %1;" : "=f"(y) : "f"(v)); return y;
}
__device__ __forceinline__ uint32_t f2tf32(float v) {
    uint32_t u; asm("cvt.rna.tf32.f32 %0, %1;" : "=r"(u) : "f"(v)); return u;
}
__device__ __forceinline__ void mma_tf32(float* c, const uint32_t* a, const uint32_t* b) {
    asm volatile("mma.sync.aligned.m16n8k8.row.col.f32.tf32.tf32.f32 "
                 "{%0,%1,%2,%3}, {%4,%5,%6,%7}, {%8,%9}, {%0,%1,%2,%3};"
                 : "+f"(c[0]), "+f"(c[1]), "+f"(c[2]), "+f"(c[3])
                 : "r"(a[0]), "r"(a[1]), "r"(a[2]), "r"(a[3]), "r"(b[0]), "r"(b[1]));
}
#define CP_COMMIT() asm volatile("cp.async.commit_group;" ::: "memory")
#define CP_WAIT1()  asm volatile("cp.async.wait_group 1;" ::: "memory")

// ---------------------------------------------------------------------------
// SMEM layout (dynamic, bytes) for gate kernel
// ---------------------------------------------------------------------------
#define SM_WP   0
#define SM_X0   131072
#define SM_X1   163840
#define SM_BW   196608
#define SM_RED  197632
#define SM_TOT  198656

__global__ void __launch_bounds__(256, 1) gate_kernel(
    const float* __restrict__ x, const float* __restrict__ Wp,
    const float* __restrict__ bp, const float* __restrict__ Wg, int ntiles)
{
    extern __shared__ char smem[];
    uint32_t*     Wps = (uint32_t*)(smem + SM_WP);
    const float*  xsf[2] = { (const float*)(smem + SM_X0), (const float*)(smem + SM_X1) };
    float2*       bwv = (float2*)(smem + SM_BW);
    float*        red = (float*)(smem + SM_RED);

    const int tid = threadIdx.x, wid = tid >> 5, lane = tid & 31;
    const int lane4 = lane >> 2, lanek = lane & 3;
    const int wm = wid & 1, wn = wid >> 1;
    const uint32_t m = (uint32_t)(lane4 << 2);     // swizzle mask (row&7)<<2 == lane4<<2

    // stage Wp with rna tf32 rounding, swizzled (float off = f ^ ((n&7)<<2))
    for (int i = tid; i < 128 * 64; i += 256) {
        const int n = i >> 6, c4 = i & 63;
        const float4 v = *(const float4*)(Wp + n * D_IN + c4 * 4);
        uint4 u;
        u.x = f2tf32(v.x); u.y = f2tf32(v.y); u.z = f2tf32(v.z); u.w = f2tf32(v.w);
        *(uint4*)((char*)Wps + n * 1024 + ((c4 ^ (n & 7)) << 4)) = u;
    }
    if (tid < 128) { float2 bw; bw.x = bp[tid]; bw.y = Wg[tid]; bwv[tid] = bw; }

    const uint32_t xs_u[2] = { smem_u32(xsf[0]), smem_u32(xsf[1]) };

    auto issue_half = [&](int tile, int h) {
        const float* xg = x + (size_t)tile * M_TILE * D_IN + h * 128;
        #pragma unroll
        for (int j = 0; j < 8; j++) {
            const int idx = tid + j * 256;            // 0..2047 float4s
            const int row = idx >> 5, c4 = idx & 31;
            const uint32_t dst = xs_u[h] + row * 512 + ((c4 ^ (row & 7)) << 4);
            asm volatile("cp.async.cg.shared.global [%0], [%1], 16;"
                         :: "r"(dst), "l"(xg + row * 256 + c4 * 4));
        }
        CP_COMMIT();
    };

    // per-thread fragment bases
    int xrow[2][2];
    #pragma unroll
    for (int mt = 0; mt < 2; mt++)
        #pragma unroll
        for (int rh = 0; rh < 2; rh++)
            xrow[mt][rh] = (wm * 32 + mt * 16 + rh * 8 + lane4) * 128;
    int bn[4];
    #pragma unroll
    for (int nt = 0; nt < 4; nt++) bn[nt] = (wn * 32 + nt * 8 + lane4) * 256;

    auto compute_half = [&](int h, float (&acc)[2][4][4]) {
        const float* xb = xsf[h];
        const int kb = h * 128;
        #pragma unroll
        for (int k0 = 0; k0 < 128; k0 += 8) {
            uint32_t a[2][4];
            #pragma unroll
            for (int mt = 0; mt < 2; mt++) {
                a[mt][0] = f2tf32(xb[xrow[mt][0] + (((k0     + lanek)) ^ m)]);
                a[mt][1] = f2tf32(xb[xrow[mt][1] + (((k0     + lanek)) ^ m)]);
                a[mt][2] = f2tf32(xb[xrow[mt][0] + (((k0 + 4 + lanek)) ^ m)]);
                a[mt][3] = f2tf32(xb[xrow[mt][1] + (((k0 + 4 + lanek)) ^ m)]);
            }
            uint32_t b[4][2];
            #pragma unroll
            for (int nt = 0; nt < 4; nt++) {
                b[nt][0] = Wps[bn[nt] + (((kb + k0     + lanek)) ^ m)];
                b[nt][1] = Wps[bn[nt] + (((kb + k0 + 4 + lanek)) ^ m)];
            }
            #pragma unroll
            for (int mt = 0; mt < 2; mt++)
                #pragma unroll
                for (int nt = 0; nt < 4; nt++)
                    mma_tf32(acc[mt][nt], a[mt], b[nt]);
        }
    };

    const int iters = (ntiles - blockIdx.x + gridDim.x - 1) / gridDim.x;
    if (iters > 0) { issue_half(blockIdx.x, 0); issue_half(blockIdx.x, 1); }

    for (int i = 0; i < iters; i++) {
        const int tile  = blockIdx.x + i * gridDim.x;
        const int ntile = tile + gridDim.x;
        float acc[2][4][4];
        #pragma unroll
        for (int mt = 0; mt < 2; mt++)
            #pragma unroll
            for (int nt = 0; nt < 4; nt++)
                #pragma unroll
                for (int c = 0; c < 4; c++) acc[mt][nt][c] = 0.f;

        // half 0
        CP_WAIT1(); __syncthreads();
        compute_half(0, acc);
        __syncthreads();
        if (i + 1 < iters) issue_half(ntile, 0); else CP_COMMIT();

        // half 1
        CP_WAIT1(); __syncthreads();
        compute_half(1, acc);

        // epilogue: s[row] = sum_col Wg[col]*tanh(P+bp[col])
        float s[2][2] = {{0.f, 0.f}, {0.f, 0.f}};
        #pragma unroll
        for (int mt = 0; mt < 2; mt++)
            #pragma unroll
            for (int nt = 0; nt < 4; nt++) {
                const int colb = wn * 32 + nt * 8 + 2 * lanek;
                const float2 bw0 = bwv[colb], bw1 = bwv[colb + 1];
                s[mt][0] = fmaf(bw0.y, tanh_fast(acc[mt][nt][0] + bw0.x),
                           fmaf(bw1.y, tanh_fast(acc[mt][nt][1] + bw1.x), s[mt][0]));
                s[mt][1] = fmaf(bw0.y, tanh_fast(acc[mt][nt][2] + bw0.x),
                           fmaf(bw1.y, tanh_fast(acc[mt][nt][3] + bw1.x), s[mt][1]));
            }
        #pragma unroll
        for (int off = 1; off <= 2; off <<= 1) {
            #pragma unroll
            for (int mt = 0; mt < 2; mt++) {
                s[mt][0] += __shfl_xor_sync(0xffffffffu, s[mt][0], off);
                s[mt][1] += __shfl_xor_sync(0xffffffffu, s[mt][1], off);
            }
        }
        if (lanek == 0) {
            #pragma unroll
            for (int mt = 0; mt < 2; mt++)
                #pragma unroll
                for (int rh = 0; rh < 2; rh++)
                    red[wn * 64 + wm * 32 + mt * 16 + rh * 8 + lane4] = s[mt][rh];
        }
        __syncthreads();
        if (tid < 64) {
            const float t = red[tid] + red[64 + tid] + red[128 + tid] + red[192 + tid];
            g_gate[tile * M_TILE + tid] = 1.f / (1.f + __expf(-t));
        }
        __syncthreads();
        if (i + 1 < iters) issue_half(ntile, 1); else CP_COMMIT();
    }
}

// ---------------------------------------------------------------------------
// Stage B: sliding causal window, window=64.
// Block = (t-tile 256, batch b). Thread = (d-group of 4 channels) x
// (t-subtile of 64). float4 loads/stores, batch-4 (128 B in flight / stream).
// Subtile prefill re-reads the neighbor subtile's stream -> L1/L2 hits.
// ---------------------------------------------------------------------------
__global__ void __launch_bounds__(256, 3) window_kernel(
    const float* __restrict__ x, float* __restrict__ out)
{
    const int b    = blockIdx.y;
    const int t0   = blockIdx.x * TT;
    const int tsub = threadIdx.x >> 6;          // 0..3
    const int dg   = threadIdx.x & 63;          // channel group (4 ch)

    __shared__ float gs[TT + W_WIN - 1];        // g[t0-63 .. t0+255]; 0 for t<0
    __shared__ float rinv[TT];
    for (int i = threadIdx.x; i < TT + W_WIN - 1; i += 256) {
        const int t = t0 - (W_WIN - 1) + i;
        gs[i] = (t >= 0) ? g_gate[b * T_LEN + t] : 0.f;
    }
    __syncthreads();
    {   // den for output index i = sum gs[i .. i+63]
        float den = 0.f;
        const int i = threadIdx.x;
        #pragma unroll 8
        for (int j = 0; j < W_WIN; j++) den += gs[i + j];
        rinv[i] = __frcp_rn(den);
    }
    __syncthreads();

    const int ts0 = t0 + tsub * 64;             // this thread's first output t
    const int gb  = tsub * 64;                  // gs base: gs[gb+j] == g[ts0-63+j]
    const float4* xb = (const float4*)(x   + ((size_t)b * T_LEN) * D_IN) + dg;
    float4*       ob = (float4*)      (out + ((size_t)b * T_LEN) * D_IN) + dg;
    const int S = D_IN / 4;                     // float4 row stride (64)

    float4 num = make_float4(0.f, 0.f, 0.f, 0.f);

    // prefill trailing window [ts0-63, ts0-1], batch-4 (last batch: 3 live)
    #pragma unroll 1
    for (int j0 = 0; j0 < W_WIN; j0 += 4) {
        float4 xa[4]; float gv[4];
        #pragma unroll
        for (int u = 0; u < 4; u++) {
            const int j = j0 + u;
            const int t = ts0 - (W_WIN - 1) + j;
            const int tc = t < 0 ? 0 : t;
            xa[u] = xb[(size_t)tc * S];
            gv[u] = (j < W_WIN - 1) ? gs[gb + j] : 0.f;   // j==63 excluded
        }
        #pragma unroll
        for (int u = 0; u < 4; u++) {
            num.x = fmaf(gv[u], xa[u].x, num.x);
            num.y = fmaf(gv[u], xa[u].y, num.y);
            num.z = fmaf(gv[u], xa[u].z, num.z);
            num.w = fmaf(gv[u], xa[u].w, num.w);
        }
    }

    // main loop: 64 outputs, batch-4
    #pragma unroll 1
    for (int j0 = 0; j0 < 64; j0 += 4) {
        float4 xa[4], xs[4];
        #pragma unroll
        for (int u = 0; u < 4; u++)
            xa[u] = xb[(size_t)(ts0 + j0 + u) * S];
        #pragma unroll
        for (int u = 0; u < 4; u++) {
            const int tr = ts0 + j0 + u - (W_WIN - 1);
            const int trc = tr < 0 ? 0 : tr;
            xs[u] = xb[(size_t)trc * S];
        }
        #pragma unroll
        for (int u = 0; u < 4; u++) {
            const int j = j0 + u;
            const float ga = gs[gb + (W_WIN - 1) + j];
            num.x = fmaf(ga, xa[u].x, num.x);
            num.y = fmaf(ga, xa[u].y, num.y);
            num.z = fmaf(ga, xa[u].z, num.z);
            num.w = fmaf(ga, xa[u].w, num.w);
            const float r = rinv[tsub * 64 + j];
            float4 o;
            o.x = num.x * r; o.y = num.y * r; o.z = num.z * r; o.w = num.w * r;
            ob[(size_t)(ts0 + j) * S] = o;
            const float gr = gs[gb + j];        // 0 when t-63 < 0
            num.x = fmaf(-gr, xs[u].x, num.x);
            num.y = fmaf(-gr, xs[u].y, num.y);
            num.z = fmaf(-gr, xs[u].z, num.z);
            num.w = fmaf(-gr, xs[u].w, num.w);
        }
    }
}

// ---------------------------------------------------------------------------
extern "C" void kernel_launch(void* const* d_in, const int* in_sizes, int n_in,
                              void* d_out, int out_size)
{
    const float* x  = (const float*)d_in[0];
    const float* Wp = (const float*)d_in[1];
    const float* bp = (const float*)d_in[2];
    const float* Wg = (const float*)d_in[3];
    float* out = (float*)d_out;

    const int rows_total = in_sizes[0] / D_IN;   // B*T
    const int ntiles = rows_total / M_TILE;      // 2048
    const int batches = rows_total / T_LEN;      // 32

    int nsm = 148;
    cudaDeviceGetAttribute(&nsm, cudaDevAttrMultiProcessorCount, 0);
    const int grid = nsm < ntiles ? nsm : ntiles;

    cudaFuncSetAttribute(gate_kernel,
                         cudaFuncAttributeMaxDynamicSharedMemorySize, SM_TOT);
    gate_kernel<<<grid, 256, SM_TOT>>>(x, Wp, bp, Wg, ntiles);

    dim3 wgrid(T_LEN / TT, batches);
    window_kernel<<<wgrid, 256>>>(x, out);
}